// round 10
// baseline (speedup 1.0000x reference)
#include <cuda_runtime.h>
#include <cuda_bf16.h>
#include <cstdint>

// Problem constants (fixed by reference setup_inputs)
#define BATCH 4096
#define CELL  400
#define CELL4 100    // CELL/4
#define KMIX  10
#define TLEN  256
#define VDIM  80
#define NT    320    // 10 warps == KMIX warps
#define JPRE  4      // first 4 of 16 t-chunks prefetched to smem (t = 0..63)
#define PRE_F4 (JPRE * 16 * 20)   // 1280 float4s = 20 KB

#define CP_ASYNC_16(smem_u32, gptr) \
    asm volatile("cp.async.cg.shared.global [%0], [%1], 16;" :: "r"(smem_u32), "l"(gptr))
#define CP_ASYNC_COMMIT()   asm volatile("cp.async.commit_group;" ::: "memory")
#define CP_ASYNC_WAIT_ALL() asm volatile("cp.async.wait_group 0;" ::: "memory")

__global__ __launch_bounds__(NT, 6)
void window_fused(const float* __restrict__ x,
                  const float* __restrict__ kappa_old,
                  const float* __restrict__ onehots,
                  const float* __restrict__ W,
                  const float* __restrict__ bias,
                  float* __restrict__ out_weight,   // [B, V]
                  float* __restrict__ out_kappa)    // [B, K]
{
    const int b    = blockIdx.x;
    const int tid  = threadIdx.x;
    const int warp = tid >> 5;
    const int lane = tid & 31;

    __shared__ float4 soh[PRE_F4];      // first 64 t-rows of onehots[b]
    __shared__ float  sal[KMIX], sbe[KMIX], ska[KMIX];
    __shared__ float  sphi[TLEN];
    __shared__ float4 wpart[16 * 20];

    const float4* oh = (const float4*)(onehots + (size_t)b * TLEN * VDIM);

    // ---- issue async prefetch of first 20KB of onehots[b] (fills during prologue)
    {
        uint32_t soh_u32 = (uint32_t)__cvta_generic_to_shared(soh);
        #pragma unroll
        for (int k = 0; k < PRE_F4 / NT; k++) {
            const int i = tid + k * NT;
            CP_ASYNC_16(soh_u32 + i * 16, oh + i);
        }
        CP_ASYNC_COMMIT();
    }

    // ---- mat-vec + transforms: warp w owns mixture component w ----
    // x[b] read as warp-broadcast LDG (L1-cached across warps); W coalesced, L2-hot.
    {
        const float4* x4 = (const float4*)(x + (size_t)b * CELL);
        const float4* W4 = (const float4*)W;
        float s0 = 0.f, s1 = 0.f, s2 = 0.f;
        #pragma unroll 4
        for (int c4 = lane; c4 < CELL4; c4 += 32) {
            const float4 xv = x4[c4];
            const float4 w0 = W4[(warp)          * CELL4 + c4];
            const float4 w1 = W4[(warp + KMIX)   * CELL4 + c4];
            const float4 w2 = W4[(warp + 2*KMIX) * CELL4 + c4];
            s0 += xv.x * w0.x + xv.y * w0.y + xv.z * w0.z + xv.w * w0.w;
            s1 += xv.x * w1.x + xv.y * w1.y + xv.z * w1.z + xv.w * w1.w;
            s2 += xv.x * w2.x + xv.y * w2.y + xv.z * w2.z + xv.w * w2.w;
        }
        #pragma unroll
        for (int off = 16; off > 0; off >>= 1) {
            s0 += __shfl_xor_sync(0xffffffffu, s0, off);
            s1 += __shfl_xor_sync(0xffffffffu, s1, off);
            s2 += __shfl_xor_sync(0xffffffffu, s2, off);
        }
        if (lane == 0) {
            // lane 0 of warp w holds the full (alpha,beta,kappa) triple for component w
            const float alpha = __expf(s0 + bias[warp]);
            const float beta  = __expf(s1 + bias[warp + KMIX]);
            const float kap   = kappa_old[(size_t)b * KMIX + warp]
                              + __expf(s2 + bias[warp + 2*KMIX]);
            sal[warp] = alpha;
            sbe[warp] = beta;
            ska[warp] = kap;
            out_kappa[(size_t)b * KMIX + warp] = kap;
        }
    }
    __syncthreads();

    // ---- phi[t] ----
    if (tid < TLEN) {
        const float u = (float)tid;
        float s = 0.0f;
        #pragma unroll
        for (int k = 0; k < KMIX; k++) {
            const float d = ska[k] - u;
            s += sal[k] * __expf(-sbe[k] * d * d);
        }
        sphi[tid] = s;
    }
    CP_ASYNC_WAIT_ALL();
    __syncthreads();

    // ---- streaming einsum: j<JPRE from smem, rest from global (proven shape) ----
    const int c  = tid % 20;    // float4 column (v/4)
    const int t0 = tid / 20;    // 0..15

    float4 acc = make_float4(0.f, 0.f, 0.f, 0.f);
    #pragma unroll
    for (int j = 0; j < JPRE; j++) {
        const int t = t0 + j * 16;
        const float  p = sphi[t];
        const float4 o = soh[t * 20 + c];
        acc.x += p * o.x; acc.y += p * o.y; acc.z += p * o.z; acc.w += p * o.w;
    }
    #pragma unroll
    for (int j = JPRE; j < 16; j++) {
        const int t = t0 + j * 16;
        const float  p = sphi[t];
        const float4 o = oh[t * 20 + c];
        acc.x += p * o.x; acc.y += p * o.y; acc.z += p * o.z; acc.w += p * o.w;
    }
    wpart[t0 * 20 + c] = acc;
    __syncthreads();

    if (tid < VDIM) {
        const float* wp = (const float*)wpart;
        float s = 0.0f;
        #pragma unroll
        for (int j = 0; j < 16; j++) s += wp[j * VDIM + tid];
        out_weight[(size_t)b * VDIM + tid] = s;
    }
}

extern "C" void kernel_launch(void* const* d_in, const int* in_sizes, int n_in,
                              void* d_out, int out_size)
{
    const float* x         = (const float*)d_in[0];   // [B, CELL]
    const float* kappa_old = (const float*)d_in[1];   // [B, K]
    const float* onehots   = (const float*)d_in[2];   // [B, T, V]
    const float* W         = (const float*)d_in[3];   // [3K, CELL]
    const float* bias      = (const float*)d_in[4];   // [3K]

    float* out_weight = (float*)d_out;                        // [B, V]
    float* out_kappa  = (float*)d_out + (size_t)BATCH * VDIM; // [B, K]

    window_fused<<<BATCH, NT>>>(x, kappa_old, onehots, W, bias,
                                out_weight, out_kappa);
}